// round 1
// baseline (speedup 1.0000x reference)
#include <cuda_runtime.h>

#define DD 512
#define NB 8
#define NQ 128
#define NK 256

// Scratch for projected q/k (graph-capture safe: static device globals)
__device__ float g_qt[NB * NQ * DD];   // 2 MB
__device__ float g_kt[NB * NK * DD];   // 4 MB

__device__ __forceinline__ float fast_tanh(float x) {
    float y;
    asm("tanh.approx.f32 %0, %1;" : "=f"(y) : "f"(x));
    return y;
}

// ---------------------------------------------------------------------------
// Projection GEMM: C[m,n] = sum_k X[m,k] * W[n,k] + bias[n],  N = K = 512.
// Virtual M = 3072: rows [0,1024) -> q_t = query@W2^T + b2
//                   rows [1024,3072) -> k_t = key@W1^T + b1
// Tile 64x64, 128 threads, 8x4 micro-tile, K-chunk 32, k-major smem (+4 pad).
// ---------------------------------------------------------------------------
#define GM 64
#define GN 64
#define GKC 32

__global__ __launch_bounds__(128) void proj_kernel(
    const float* __restrict__ query, const float* __restrict__ key,
    const float* __restrict__ W1, const float* __restrict__ b1,
    const float* __restrict__ W2, const float* __restrict__ b2)
{
    __shared__ float Xs[GKC][GM + 4];
    __shared__ float Ws[GKC][GN + 4];

    const int m0 = blockIdx.x * GM;
    const int n0 = blockIdx.y * GN;

    const float *X, *W, *bias;
    float* out;
    if (m0 < NB * NQ) {
        X = query + m0 * DD; W = W2; bias = b2; out = g_qt + m0 * DD;
    } else {
        X = key + (m0 - NB * NQ) * DD; W = W1; bias = b1;
        out = g_kt + (m0 - NB * NQ) * DD;
    }

    const int tid = threadIdx.x;
    const int tx = tid & 15;   // col group (0..15), 4 cols each
    const int ty = tid >> 4;   // row group (0..7),  8 rows each

    float acc[8][4];
#pragma unroll
    for (int i = 0; i < 8; i++)
#pragma unroll
        for (int j = 0; j < 4; j++) acc[i][j] = 0.0f;

    for (int kc = 0; kc < DD; kc += GKC) {
        // Load X chunk (64x32) transposed into k-major smem: 4 float4/thread
#pragma unroll
        for (int i = 0; i < 4; i++) {
            int idx = tid + i * 128;            // 0..511
            int r = idx >> 3, fc = idx & 7;
            float4 t = *reinterpret_cast<const float4*>(&X[r * DD + kc + fc * 4]);
            Xs[fc * 4 + 0][r] = t.x; Xs[fc * 4 + 1][r] = t.y;
            Xs[fc * 4 + 2][r] = t.z; Xs[fc * 4 + 3][r] = t.w;
        }
        // Load W chunk (64x32) transposed
#pragma unroll
        for (int i = 0; i < 4; i++) {
            int idx = tid + i * 128;
            int r = idx >> 3, fc = idx & 7;
            float4 t = *reinterpret_cast<const float4*>(&W[(n0 + r) * DD + kc + fc * 4]);
            Ws[fc * 4 + 0][r] = t.x; Ws[fc * 4 + 1][r] = t.y;
            Ws[fc * 4 + 2][r] = t.z; Ws[fc * 4 + 3][r] = t.w;
        }
        __syncthreads();

#pragma unroll
        for (int kk = 0; kk < GKC; kk++) {
            float4 a0 = *reinterpret_cast<const float4*>(&Xs[kk][ty * 8]);
            float4 a1 = *reinterpret_cast<const float4*>(&Xs[kk][ty * 8 + 4]);
            float4 bw = *reinterpret_cast<const float4*>(&Ws[kk][tx * 4]);
            float xr[8] = {a0.x, a0.y, a0.z, a0.w, a1.x, a1.y, a1.z, a1.w};
            float wr[4] = {bw.x, bw.y, bw.z, bw.w};
#pragma unroll
            for (int i = 0; i < 8; i++)
#pragma unroll
                for (int j = 0; j < 4; j++)
                    acc[i][j] = fmaf(xr[i], wr[j], acc[i][j]);
        }
        __syncthreads();
    }

    float4 bb = *reinterpret_cast<const float4*>(&bias[n0 + tx * 4]);
#pragma unroll
    for (int i = 0; i < 8; i++) {
        float4 o;
        o.x = acc[i][0] + bb.x; o.y = acc[i][1] + bb.y;
        o.z = acc[i][2] + bb.z; o.w = acc[i][3] + bb.w;
        *reinterpret_cast<float4*>(&out[(ty * 8 + i) * DD + n0 + tx * 4]) = o;
    }
}

// ---------------------------------------------------------------------------
// Score kernel: scores[b,q,k] = sum_d v[d] * tanh(qt[b,q,d] + kt[b,k,d])
// Block tile: 32 q x 64 k, 256 threads, 2x4 register tile, D chunked by 64.
// MUFU(tanh)-bound by design: per d-step each warp issues 8 MUFU vs 16 FFMA.
// ---------------------------------------------------------------------------
#define SQ 32
#define SK 64
#define SD 64

__global__ __launch_bounds__(256) void score_kernel(
    const float* __restrict__ v, float* __restrict__ out)
{
    __shared__ float qs[SQ][SD + 1];
    __shared__ float ks[SK][SD + 1];
    __shared__ float vs[SD];

    const int b  = blockIdx.z;
    const int q0 = blockIdx.y * SQ;
    const int k0 = blockIdx.x * SK;
    const float* qt = g_qt + (b * NQ + q0) * DD;
    const float* kt = g_kt + (b * NK + k0) * DD;

    const int tid = threadIdx.x;
    const int tk = tid & 15;   // 4 k-cols each
    const int tq = tid >> 4;   // 2 q-rows each

    float acc[2][4] = {{0.f, 0.f, 0.f, 0.f}, {0.f, 0.f, 0.f, 0.f}};

    for (int dc = 0; dc < DD; dc += SD) {
        // qs: 32x64 floats = 512 float4, 2 per thread
#pragma unroll
        for (int i = 0; i < 2; i++) {
            int idx = tid + i * 256;
            int r = idx >> 4, fc = idx & 15;
            float4 t = *reinterpret_cast<const float4*>(&qt[r * DD + dc + fc * 4]);
            qs[r][fc * 4 + 0] = t.x; qs[r][fc * 4 + 1] = t.y;
            qs[r][fc * 4 + 2] = t.z; qs[r][fc * 4 + 3] = t.w;
        }
        // ks: 64x64 floats = 1024 float4, 4 per thread
#pragma unroll
        for (int i = 0; i < 4; i++) {
            int idx = tid + i * 256;
            int r = idx >> 4, fc = idx & 15;
            float4 t = *reinterpret_cast<const float4*>(&kt[r * DD + dc + fc * 4]);
            ks[r][fc * 4 + 0] = t.x; ks[r][fc * 4 + 1] = t.y;
            ks[r][fc * 4 + 2] = t.z; ks[r][fc * 4 + 3] = t.w;
        }
        if (tid < SD) vs[tid] = v[dc + tid];
        __syncthreads();

#pragma unroll 8
        for (int dd = 0; dd < SD; dd++) {
            float vq0 = qs[tq * 2 + 0][dd];
            float vq1 = qs[tq * 2 + 1][dd];
            float kv0 = ks[tk * 4 + 0][dd];
            float kv1 = ks[tk * 4 + 1][dd];
            float kv2 = ks[tk * 4 + 2][dd];
            float kv3 = ks[tk * 4 + 3][dd];
            float vd  = vs[dd];
            acc[0][0] = fmaf(vd, fast_tanh(vq0 + kv0), acc[0][0]);
            acc[0][1] = fmaf(vd, fast_tanh(vq0 + kv1), acc[0][1]);
            acc[0][2] = fmaf(vd, fast_tanh(vq0 + kv2), acc[0][2]);
            acc[0][3] = fmaf(vd, fast_tanh(vq0 + kv3), acc[0][3]);
            acc[1][0] = fmaf(vd, fast_tanh(vq1 + kv0), acc[1][0]);
            acc[1][1] = fmaf(vd, fast_tanh(vq1 + kv1), acc[1][1]);
            acc[1][2] = fmaf(vd, fast_tanh(vq1 + kv2), acc[1][2]);
            acc[1][3] = fmaf(vd, fast_tanh(vq1 + kv3), acc[1][3]);
        }
        __syncthreads();
    }

#pragma unroll
    for (int i = 0; i < 2; i++) {
        float4 o;
        o.x = acc[i][0]; o.y = acc[i][1]; o.z = acc[i][2]; o.w = acc[i][3];
        *reinterpret_cast<float4*>(
            &out[(b * NQ + q0 + tq * 2 + i) * NK + k0 + tk * 4]) = o;
    }
}

extern "C" void kernel_launch(void* const* d_in, const int* in_sizes, int n_in,
                              void* d_out, int out_size)
{
    const float* query = (const float*)d_in[0];  // [8,128,512]
    const float* key   = (const float*)d_in[1];  // [8,256,512]
    const float* W1    = (const float*)d_in[2];  // [512,512]
    const float* b1    = (const float*)d_in[3];  // [512]
    const float* W2    = (const float*)d_in[4];  // [512,512]
    const float* b2    = (const float*)d_in[5];  // [512]
    const float* v     = (const float*)d_in[6];  // [512]
    float* out = (float*)d_out;                  // [8,128,256]

    // Virtual M = 3072 rows (1024 q + 2048 k): 48 m-tiles x 8 n-tiles
    proj_kernel<<<dim3(48, 8), 128>>>(query, key, W1, b1, W2, b2);
    // 4 k-tiles x 4 q-tiles x 8 batches = 128 blocks
    score_kernel<<<dim3(NK / SK, NQ / SQ, NB), 256>>>(v, out);
}